// round 7
// baseline (speedup 1.0000x reference)
#include <cuda_runtime.h>
#include <cstdint>
#include <math.h>

// ---------------- problem constants ----------------
#define BATCH 4
#define SEQ   2048
#define DIM   512
#define WIN   64
#define QT    32

// attention smem layout
#define TP 516                 // tile row pitch (floats): conflict-free strided row loads
#define SROWS 96
#define SP 100                 // score row pitch

// gemm tiling (mma.sync tf32 m16n8k8); each half-GEMM has K=512
#define GM 128
#define GN 128
#define KC 32
#define NCHUNK2 (512 / KC)     // 16 chunks per half
#define APADW 36
#define BPADW 136              // b-frag banks 8*tig+gid all distinct
#define AFL (GM * APADW)       // 4608
#define BFL (KC * BPADW)       // 4352
#define STF (AFL + BFL)        // 8960 floats per stage
#define NSTAGE 3

// device scratch (no cudaMalloc allowed)
__device__ float g_c[BATCH * SEQ * DIM];   // attention context
__device__ float g_z[BATCH * SEQ * DIM];   // partial pre-sigmoid logits (x-half)

__device__ __forceinline__ uint32_t smem_u32(const void* p) {
    uint32_t a;
    asm("{ .reg .u64 t; cvta.to.shared.u64 t, %1; cvt.u32.u64 %0, t; }"
        : "=r"(a) : "l"(p));
    return a;
}
__device__ __forceinline__ void cpa16(uint32_t d, const float* s) {
    asm volatile("cp.async.cg.shared.global [%0], [%1], 16;" :: "r"(d), "l"(s));
}

extern __shared__ float sm_dyn[];

// ---------------------------------------------------------------------------
// Attention: 256 CTAs, 256 threads, QT=32 queries each. (unchanged from R6)
// ---------------------------------------------------------------------------
__global__ __launch_bounds__(256) void attn_kernel(const float* __restrict__ x) {
    float* tile = sm_dyn;                 // [96][TP]
    float* S    = sm_dyn + SROWS * TP;    // [32][SP]

    const int tid = threadIdx.x;
    const int b   = blockIdx.x >> 6;
    const int qs  = (blockIdx.x & 63) * QT;
    const float* xb = x + (size_t)b * SEQ * DIM;

#pragma unroll 8
    for (int p = 0; p < 48; p++) {
        const int idx = tid + 256 * p;
        const int r   = idx >> 7;
        const int c4  = (idx & 127) << 2;
        const int gr  = qs - WIN + r;
        float4 v = make_float4(0.f, 0.f, 0.f, 0.f);
        if (gr >= 0)
            v = *reinterpret_cast<const float4*>(xb + (size_t)gr * DIM + c4);
        *reinterpret_cast<float4*>(tile + r * TP + c4) = v;
    }
    __syncthreads();

    const int ty = tid >> 5;
    const int tx = tid & 31;

    // phase 1: dense S[i][j] = <tile[64+i], tile[j]>
    {
        float sa[4][3];
#pragma unroll
        for (int i = 0; i < 4; i++)
#pragma unroll
            for (int j = 0; j < 3; j++) sa[i][j] = 0.f;

        const float* q0 = tile + (WIN + 4 * ty) * TP;
        const float* k0 = tile + tx * TP;
#pragma unroll 2
        for (int d = 0; d < DIM; d += 4) {
            float4 q[4], k[3];
#pragma unroll
            for (int ii = 0; ii < 4; ii++)
                q[ii] = *reinterpret_cast<const float4*>(q0 + ii * TP + d);
#pragma unroll
            for (int jj = 0; jj < 3; jj++)
                k[jj] = *reinterpret_cast<const float4*>(k0 + jj * 32 * TP + d);
#pragma unroll
            for (int ii = 0; ii < 4; ii++)
#pragma unroll
                for (int jj = 0; jj < 3; jj++) {
                    sa[ii][jj] = fmaf(q[ii].x, k[jj].x, sa[ii][jj]);
                    sa[ii][jj] = fmaf(q[ii].y, k[jj].y, sa[ii][jj]);
                    sa[ii][jj] = fmaf(q[ii].z, k[jj].z, sa[ii][jj]);
                    sa[ii][jj] = fmaf(q[ii].w, k[jj].w, sa[ii][jj]);
                }
        }
#pragma unroll
        for (int ii = 0; ii < 4; ii++)
#pragma unroll
            for (int jj = 0; jj < 3; jj++)
                S[(4 * ty + ii) * SP + tx + 32 * jj] = sa[ii][jj];
    }
    __syncthreads();

    // phase 2: band softmax in-place -> dense alpha (zeros outside band)
    {
        const int i = tid >> 3;
        const int g = tid & 7;
        float* srow = S + i * SP;
        float m = -1e30f;
        float vals[8];
#pragma unroll
        for (int w8 = 0; w8 < 8; w8++) {
            vals[w8] = srow[i + g + 8 * w8];
            m = fmaxf(m, vals[w8]);
        }
        m = fmaxf(m, __shfl_xor_sync(0xffffffffu, m, 1));
        m = fmaxf(m, __shfl_xor_sync(0xffffffffu, m, 2));
        m = fmaxf(m, __shfl_xor_sync(0xffffffffu, m, 4));
        float s = 0.f;
#pragma unroll
        for (int w8 = 0; w8 < 8; w8++) s += __expf(vals[w8] - m);
        s += __shfl_xor_sync(0xffffffffu, s, 1);
        s += __shfl_xor_sync(0xffffffffu, s, 2);
        s += __shfl_xor_sync(0xffffffffu, s, 4);
        const float inv = 1.f / s;
        __syncwarp();
#pragma unroll
        for (int jj = 0; jj < 12; jj++) {
            const int j = g * 12 + jj;
            float v = 0.f;
            if (j >= i && j < i + WIN) v = __expf(srow[j] - m) * inv;
            srow[j] = v;
        }
    }
    __syncthreads();

    // phase 3: context
    {
        float cacc[4][16];
#pragma unroll
        for (int i = 0; i < 4; i++)
#pragma unroll
            for (int d = 0; d < 16; d++) cacc[i][d] = 0.f;

        const float* arow = S + 4 * ty * SP;
        for (int j = 0; j < 68; j++) {
            const int jj = 4 * ty + j;
            float a[4];
#pragma unroll
            for (int ii = 0; ii < 4; ii++) a[ii] = arow[ii * SP + jj];
            const float* kr = tile + jj * TP + 4 * tx;
#pragma unroll
            for (int q = 0; q < 4; q++) {
                float4 kv = *reinterpret_cast<const float4*>(kr + 128 * q);
#pragma unroll
                for (int ii = 0; ii < 4; ii++) {
                    cacc[ii][4 * q + 0] = fmaf(a[ii], kv.x, cacc[ii][4 * q + 0]);
                    cacc[ii][4 * q + 1] = fmaf(a[ii], kv.y, cacc[ii][4 * q + 1]);
                    cacc[ii][4 * q + 2] = fmaf(a[ii], kv.z, cacc[ii][4 * q + 2]);
                    cacc[ii][4 * q + 3] = fmaf(a[ii], kv.w, cacc[ii][4 * q + 3]);
                }
            }
        }
#pragma unroll
        for (int ii = 0; ii < 4; ii++) {
            float* crow = g_c + ((size_t)b * SEQ + qs + 4 * ty + ii) * DIM + 4 * tx;
#pragma unroll
            for (int q = 0; q < 4; q++) {
                float4 v = make_float4(cacc[ii][4 * q], cacc[ii][4 * q + 1],
                                       cacc[ii][4 * q + 2], cacc[ii][4 * q + 3]);
                *reinterpret_cast<float4*>(crow + 128 * q) = v;
            }
        }
    }
}

// ---------------------------------------------------------------------------
// Half-GEMM (K=512): CPART=false -> z1 = x @ Wc[512:] into g_z (no sigmoid).
//                    CPART=true  -> out = sigmoid(g_z + c @ Wc[:512]).
// CTA 128x128, 256 threads, warp tile 64x32, 3-stage cp.async pipeline.
// ---------------------------------------------------------------------------
__device__ __forceinline__ void mma_tf32(float* c, uint32_t a0, uint32_t a1,
                                         uint32_t a2, uint32_t a3,
                                         uint32_t b0, uint32_t b1) {
    asm volatile(
        "mma.sync.aligned.m16n8k8.row.col.f32.tf32.tf32.f32 "
        "{%0,%1,%2,%3}, {%4,%5,%6,%7}, {%8,%9}, {%0,%1,%2,%3};"
        : "+f"(c[0]), "+f"(c[1]), "+f"(c[2]), "+f"(c[3])
        : "r"(a0), "r"(a1), "r"(a2), "r"(a3), "r"(b0), "r"(b1));
}

template <bool CPART>
__device__ __forceinline__ void issue_chunk(int c, int bm, int bn, int tid,
                                            const float* __restrict__ x,
                                            const float* __restrict__ Wc) {
    float* Ad = sm_dyn + (c % NSTAGE) * STF;
    float* Bd = Ad + AFL;
    const float* Asrc = CPART ? g_c : x;
    const int koff  = c * KC;
    const int wrow0 = (CPART ? 0 : 512) + c * KC;
    // A tile: 128 rows x 32 floats = 1024 x 16B
#pragma unroll
    for (int p = 0; p < 4; p++) {
        const int idx = tid + 256 * p;
        const int r   = idx >> 3;
        const int seg = (idx & 7) * 4;
        cpa16(smem_u32(Ad + r * APADW + seg),
              Asrc + (size_t)(bm + r) * DIM + koff + seg);
    }
    // B tile: 32 rows x 128 floats = 1024 x 16B
#pragma unroll
    for (int p = 0; p < 4; p++) {
        const int idx = tid + 256 * p;
        const int k   = idx >> 5;
        const int n4  = (idx & 31) * 4;
        cpa16(smem_u32(Bd + k * BPADW + n4),
              Wc + (size_t)(wrow0 + k) * DIM + bn + n4);
    }
    asm volatile("cp.async.commit_group;" ::: "memory");
}

template <bool CPART>
__global__ __launch_bounds__(256, 2) void gemm_half(const float* __restrict__ x,
                                                    const float* __restrict__ Wc,
                                                    float* __restrict__ outp) {
    const int tid  = threadIdx.x;
    const int wid  = tid >> 5;
    const int lane = tid & 31;
    const int gid  = lane >> 2;
    const int tig  = lane & 3;
    const int wm   = wid & 1;
    const int wn   = wid >> 1;
    const int bm   = blockIdx.y * GM;
    const int bn   = blockIdx.x * GN;

    float acc[4][4][4];
#pragma unroll
    for (int i = 0; i < 4; i++)
#pragma unroll
        for (int j = 0; j < 4; j++)
#pragma unroll
            for (int k = 0; k < 4; k++) acc[i][j][k] = 0.f;

    issue_chunk<CPART>(0, bm, bn, tid, x, Wc);
    issue_chunk<CPART>(1, bm, bn, tid, x, Wc);

    for (int c = 0; c < NCHUNK2; c++) {
        if (c == NCHUNK2 - 1)
            asm volatile("cp.async.wait_group 0;" ::: "memory");
        else
            asm volatile("cp.async.wait_group 1;" ::: "memory");
        __syncthreads();
        if (c + 2 < NCHUNK2) issue_chunk<CPART>(c + 2, bm, bn, tid, x, Wc);

        const uint32_t* Asu = reinterpret_cast<const uint32_t*>(
            sm_dyn + (c % NSTAGE) * STF);
        const uint32_t* Bsu = Asu + AFL;
#pragma unroll
        for (int kk = 0; kk < KC; kk += 8) {
            uint32_t a[4][4], bfr[4][2];
#pragma unroll
            for (int ma = 0; ma < 4; ma++) {
                const int r = wm * 64 + ma * 16 + gid;
                a[ma][0] = Asu[r * APADW + kk + tig];
                a[ma][1] = Asu[(r + 8) * APADW + kk + tig];
                a[ma][2] = Asu[r * APADW + kk + 4 + tig];
                a[ma][3] = Asu[(r + 8) * APADW + kk + 4 + tig];
            }
#pragma unroll
            for (int na = 0; na < 4; na++) {
                const int n = wn * 32 + na * 8 + gid;
                bfr[na][0] = Bsu[(kk + tig) * BPADW + n];
                bfr[na][1] = Bsu[(kk + tig + 4) * BPADW + n];
            }
#pragma unroll
            for (int ma = 0; ma < 4; ma++)
#pragma unroll
                for (int na = 0; na < 4; na++)
                    mma_tf32(acc[ma][na], a[ma][0], a[ma][1], a[ma][2], a[ma][3],
                             bfr[na][0], bfr[na][1]);
        }
    }

    // ---- epilogue ----
#pragma unroll
    for (int ma = 0; ma < 4; ma++) {
#pragma unroll
        for (int na = 0; na < 4; na++) {
            const int row = bm + wm * 64 + ma * 16 + gid;
            const int col = bn + wn * 32 + na * 8 + 2 * tig;
            if (!CPART) {
                // store raw partial logits to g_z
                float2 v0 = make_float2(acc[ma][na][0], acc[ma][na][1]);
                float2 v1 = make_float2(acc[ma][na][2], acc[ma][na][3]);
                *reinterpret_cast<float2*>(g_z + (size_t)row * DIM + col) = v0;
                *reinterpret_cast<float2*>(g_z + (size_t)(row + 8) * DIM + col) = v1;
            } else {
                float2 z0 = *reinterpret_cast<const float2*>(g_z + (size_t)row * DIM + col);
                float2 z1 = *reinterpret_cast<const float2*>(g_z + (size_t)(row + 8) * DIM + col);
                float2 v0, v1;
                v0.x = 1.f / (1.f + __expf(-(acc[ma][na][0] + z0.x)));
                v0.y = 1.f / (1.f + __expf(-(acc[ma][na][1] + z0.y)));
                v1.x = 1.f / (1.f + __expf(-(acc[ma][na][2] + z1.x)));
                v1.y = 1.f / (1.f + __expf(-(acc[ma][na][3] + z1.y)));
                *reinterpret_cast<float2*>(outp + (size_t)row * DIM + col) = v0;
                *reinterpret_cast<float2*>(outp + (size_t)(row + 8) * DIM + col) = v1;
            }
        }
    }
}

extern "C" void kernel_launch(void* const* d_in, const int* in_sizes, int n_in,
                              void* d_out, int out_size) {
    const float* x  = (const float*)d_in[0];   // (4, 2048, 512) fp32
    const float* Wc = (const float*)d_in[1];   // (1024, 512) fp32
    float* out = (float*)d_out;                // (4, 2048, 512) fp32

    // one-time side resources (host-side objects; created outside capture on
    // the first/correctness call, reused identically on every call)
    static cudaStream_t s2 = nullptr;
    static cudaEvent_t ev_fork = nullptr, ev_join = nullptr;
    if (s2 == nullptr) {
        cudaStreamCreateWithFlags(&s2, cudaStreamNonBlocking);
        cudaEventCreateWithFlags(&ev_fork, cudaEventDisableTiming);
        cudaEventCreateWithFlags(&ev_join, cudaEventDisableTiming);
    }

    const size_t attn_smem = (size_t)(SROWS * TP + QT * SP) * sizeof(float); // 210,944 B
    cudaFuncSetAttribute(attn_kernel, cudaFuncAttributeMaxDynamicSharedMemorySize,
                         (int)attn_smem);
    const size_t gemm_smem = (size_t)(NSTAGE * STF) * sizeof(float);  // 107,520 B
    cudaFuncSetAttribute(gemm_half<false>, cudaFuncAttributeMaxDynamicSharedMemorySize,
                         (int)gemm_smem);
    cudaFuncSetAttribute(gemm_half<true>, cudaFuncAttributeMaxDynamicSharedMemorySize,
                         (int)gemm_smem);

    dim3 grid(DIM / GN, (BATCH * SEQ) / GM);   // (4, 64)

    // fork: x-half GEMM (independent of attention) runs on s2 concurrently
    cudaEventRecord(ev_fork, 0);
    cudaStreamWaitEvent(s2, ev_fork, 0);
    gemm_half<false><<<grid, 256, gemm_smem, s2>>>(x, Wc, nullptr);
    cudaEventRecord(ev_join, s2);

    // attention on the main (captured) stream
    attn_kernel<<<BATCH * (SEQ / QT), 256, attn_smem>>>(x);

    // join, then the c-half GEMM + sigmoid
    cudaStreamWaitEvent(0, ev_join, 0);
    gemm_half<true><<<grid, 256, gemm_smem>>>(x, Wc, out);
}

// round 8
// speedup vs baseline: 1.1755x; 1.1755x over previous
#include <cuda_runtime.h>
#include <cstdint>
#include <math.h>

// ---------------- problem constants ----------------
#define BATCH 4
#define SEQ   2048
#define DIM   512
#define WIN   64
#define QT    32

// attention smem layout (D processed in 2 chunks of 256)
#define DC    256              // d-chunk width
#define TP2   260              // tile row pitch (floats); 260%32=4 -> conflict-free LDS.128
#define SROWS 96
#define SP    100              // score row pitch

// gemm tiling (mma.sync tf32 m16n8k8), fused K=1024
#define GM 128
#define GN 128
#define KC 32
#define NCHUNK (1024 / KC)     // 32
#define APADW 36
#define BPADW 136              // b-frag banks 8*tig+gid all distinct
#define AFL (GM * APADW)       // 4608
#define BFL (KC * BPADW)       // 4352
#define STF (AFL + BFL)        // 8960 floats per stage
#define NSTAGE 3

// context scratch [B*S, D] fp32 (no cudaMalloc allowed)
__device__ float g_c[BATCH * SEQ * DIM];

__device__ __forceinline__ uint32_t smem_u32(const void* p) {
    uint32_t a;
    asm("{ .reg .u64 t; cvta.to.shared.u64 t, %1; cvt.u32.u64 %0, t; }"
        : "=r"(a) : "l"(p));
    return a;
}
__device__ __forceinline__ void cpa16(uint32_t d, const float* s) {
    asm volatile("cp.async.cg.shared.global [%0], [%1], 16;" :: "r"(d), "l"(s));
}

extern __shared__ float sm_dyn[];

// ---------------------------------------------------------------------------
// Attention: 256 CTAs, 256 threads, QT=32 queries each, 2 CTAs/SM.
// Window tile processed in two 256-wide D chunks (smem 112,640 B).
// Window = strictly-causal left 64; zero-padded head rows score exactly 0 and
// are included in the softmax (matches reference).
// ---------------------------------------------------------------------------
__global__ __launch_bounds__(256, 2) void attn_kernel(const float* __restrict__ x) {
    float* tile = sm_dyn;                 // [96][TP2]
    float* S    = sm_dyn + SROWS * TP2;   // [32][SP]

    const int tid = threadIdx.x;
    const int b   = blockIdx.x >> 6;
    const int qs  = (blockIdx.x & 63) * QT;
    const float* xb = x + (size_t)b * SEQ * DIM;

    const int ty = tid >> 5;     // warp id (i-group of 4)
    const int tx = tid & 31;     // lane

    // loads rows qs-64 .. qs+31, cols [d0, d0+256); zero before sequence start
    auto load_tile = [&](int d0) {
#pragma unroll 8
        for (int p = 0; p < 24; p++) {
            const int idx = tid + 256 * p;
            const int r   = idx >> 6;            // 64 float4 per row
            const int c4  = (idx & 63) << 2;
            const int gr  = qs - WIN + r;
            float4 v = make_float4(0.f, 0.f, 0.f, 0.f);
            if (gr >= 0)
                v = *reinterpret_cast<const float4*>(xb + (size_t)gr * DIM + d0 + c4);
            *reinterpret_cast<float4*>(tile + r * TP2 + c4) = v;
        }
    };

    // ---- phase 1: dense S[i][j] = <tile[64+i], tile[j]>, acc over 2 d-chunks ----
    float sa[4][3];
#pragma unroll
    for (int i = 0; i < 4; i++)
#pragma unroll
        for (int j = 0; j < 3; j++) sa[i][j] = 0.f;

#pragma unroll
    for (int ch = 0; ch < 2; ch++) {
        if (ch) __syncthreads();     // everyone done reading previous chunk
        load_tile(ch * DC);
        __syncthreads();

        const float* q0 = tile + (WIN + 4 * ty) * TP2;
        const float* k0 = tile + tx * TP2;
#pragma unroll 2
        for (int d = 0; d < DC; d += 4) {
            float4 q[4], k[3];
#pragma unroll
            for (int ii = 0; ii < 4; ii++)
                q[ii] = *reinterpret_cast<const float4*>(q0 + ii * TP2 + d);
#pragma unroll
            for (int jj = 0; jj < 3; jj++)
                k[jj] = *reinterpret_cast<const float4*>(k0 + jj * 32 * TP2 + d);
#pragma unroll
            for (int ii = 0; ii < 4; ii++)
#pragma unroll
                for (int jj = 0; jj < 3; jj++) {
                    sa[ii][jj] = fmaf(q[ii].x, k[jj].x, sa[ii][jj]);
                    sa[ii][jj] = fmaf(q[ii].y, k[jj].y, sa[ii][jj]);
                    sa[ii][jj] = fmaf(q[ii].z, k[jj].z, sa[ii][jj]);
                    sa[ii][jj] = fmaf(q[ii].w, k[jj].w, sa[ii][jj]);
                }
        }
    }
#pragma unroll
    for (int ii = 0; ii < 4; ii++)
#pragma unroll
        for (int jj = 0; jj < 3; jj++)
            S[(4 * ty + ii) * SP + tx + 32 * jj] = sa[ii][jj];
    __syncthreads();

    // ---- phase 2: band softmax in-place -> dense alpha (zeros outside band) ----
    {
        const int i = tid >> 3;
        const int g = tid & 7;
        float* srow = S + i * SP;
        float m = -1e30f;
        float vals[8];
#pragma unroll
        for (int w8 = 0; w8 < 8; w8++) {
            vals[w8] = srow[i + g + 8 * w8];   // j = i + w, w in [0,64)
            m = fmaxf(m, vals[w8]);
        }
        m = fmaxf(m, __shfl_xor_sync(0xffffffffu, m, 1));
        m = fmaxf(m, __shfl_xor_sync(0xffffffffu, m, 2));
        m = fmaxf(m, __shfl_xor_sync(0xffffffffu, m, 4));
        float s = 0.f;
#pragma unroll
        for (int w8 = 0; w8 < 8; w8++) s += __expf(vals[w8] - m);
        s += __shfl_xor_sync(0xffffffffu, s, 1);
        s += __shfl_xor_sync(0xffffffffu, s, 2);
        s += __shfl_xor_sync(0xffffffffu, s, 4);
        const float inv = 1.f / s;
        __syncwarp();
#pragma unroll
        for (int jj = 0; jj < 12; jj++) {
            const int j = g * 12 + jj;
            float v = 0.f;
            if (j >= i && j < i + WIN) v = __expf(srow[j] - m) * inv;
            srow[j] = v;
        }
    }

    // ---- phase 3: context per d-chunk, c[i][d] = sum_j A[i][j]*tile[j][d] ----
#pragma unroll
    for (int ch = 0; ch < 2; ch++) {
        __syncthreads();             // phase-2 S writes visible / prev chunk done
        load_tile(ch * DC);
        __syncthreads();

        float cacc[4][8];
#pragma unroll
        for (int i = 0; i < 4; i++)
#pragma unroll
            for (int d = 0; d < 8; d++) cacc[i][d] = 0.f;

        const float* arow = S + 4 * ty * SP;
        for (int j = 0; j < 68; j++) {
            const int jj = 4 * ty + j;
            float a[4];
#pragma unroll
            for (int ii = 0; ii < 4; ii++) a[ii] = arow[ii * SP + jj];
            const float* kr = tile + jj * TP2 + 4 * tx;
#pragma unroll
            for (int q = 0; q < 2; q++) {
                float4 kv = *reinterpret_cast<const float4*>(kr + 128 * q);
#pragma unroll
                for (int ii = 0; ii < 4; ii++) {
                    cacc[ii][4 * q + 0] = fmaf(a[ii], kv.x, cacc[ii][4 * q + 0]);
                    cacc[ii][4 * q + 1] = fmaf(a[ii], kv.y, cacc[ii][4 * q + 1]);
                    cacc[ii][4 * q + 2] = fmaf(a[ii], kv.z, cacc[ii][4 * q + 2]);
                    cacc[ii][4 * q + 3] = fmaf(a[ii], kv.w, cacc[ii][4 * q + 3]);
                }
            }
        }
#pragma unroll
        for (int ii = 0; ii < 4; ii++) {
            float* crow = g_c + ((size_t)b * SEQ + qs + 4 * ty + ii) * DIM
                        + ch * DC + 4 * tx;
#pragma unroll
            for (int q = 0; q < 2; q++) {
                float4 v = make_float4(cacc[ii][4 * q], cacc[ii][4 * q + 1],
                                       cacc[ii][4 * q + 2], cacc[ii][4 * q + 3]);
                *reinterpret_cast<float4*>(crow + 128 * q) = v;
            }
        }
    }
}

// ---------------------------------------------------------------------------
// Output head: out = sigmoid([c | x] @ Wc) via mma.sync tf32 m16n8k8.
// CTA 128x128, 256 threads, warp tile 64x32, 3-stage cp.async. (R6, measured)
// ---------------------------------------------------------------------------
__device__ __forceinline__ void mma_tf32(float* c, uint32_t a0, uint32_t a1,
                                         uint32_t a2, uint32_t a3,
                                         uint32_t b0, uint32_t b1) {
    asm volatile(
        "mma.sync.aligned.m16n8k8.row.col.f32.tf32.tf32.f32 "
        "{%0,%1,%2,%3}, {%4,%5,%6,%7}, {%8,%9}, {%0,%1,%2,%3};"
        : "+f"(c[0]), "+f"(c[1]), "+f"(c[2]), "+f"(c[3])
        : "r"(a0), "r"(a1), "r"(a2), "r"(a3), "r"(b0), "r"(b1));
}

__device__ __forceinline__ void issue_chunk(int c, int bm, int bn, int tid,
                                            const float* __restrict__ x,
                                            const float* __restrict__ Wc) {
    float* Ad = sm_dyn + (c % NSTAGE) * STF;
    float* Bd = Ad + AFL;
    const float* Asrc = (c < 16) ? g_c : x;
    const int koff = (c < 16) ? c * KC : c * KC - 512;
#pragma unroll
    for (int p = 0; p < 4; p++) {
        const int idx = tid + 256 * p;
        const int r   = idx >> 3;
        const int seg = (idx & 7) * 4;
        cpa16(smem_u32(Ad + r * APADW + seg),
              Asrc + (size_t)(bm + r) * DIM + koff + seg);
    }
#pragma unroll
    for (int p = 0; p < 4; p++) {
        const int idx = tid + 256 * p;
        const int k   = idx >> 5;
        const int n4  = (idx & 31) * 4;
        cpa16(smem_u32(Bd + k * BPADW + n4),
              Wc + (size_t)(c * KC + k) * DIM + bn + n4);
    }
    asm volatile("cp.async.commit_group;" ::: "memory");
}

__global__ __launch_bounds__(256, 2) void gemm_mma(const float* __restrict__ x,
                                                   const float* __restrict__ Wc,
                                                   float* __restrict__ out) {
    const int tid  = threadIdx.x;
    const int wid  = tid >> 5;
    const int lane = tid & 31;
    const int gid  = lane >> 2;
    const int tig  = lane & 3;
    const int wm   = wid & 1;
    const int wn   = wid >> 1;
    const int bm   = blockIdx.y * GM;
    const int bn   = blockIdx.x * GN;

    float acc[4][4][4];
#pragma unroll
    for (int i = 0; i < 4; i++)
#pragma unroll
        for (int j = 0; j < 4; j++)
#pragma unroll
            for (int k = 0; k < 4; k++) acc[i][j][k] = 0.f;

    issue_chunk(0, bm, bn, tid, x, Wc);
    issue_chunk(1, bm, bn, tid, x, Wc);

    for (int c = 0; c < NCHUNK; c++) {
        if (c == NCHUNK - 1)
            asm volatile("cp.async.wait_group 0;" ::: "memory");
        else
            asm volatile("cp.async.wait_group 1;" ::: "memory");
        __syncthreads();
        if (c + 2 < NCHUNK) issue_chunk(c + 2, bm, bn, tid, x, Wc);

        const uint32_t* Asu = reinterpret_cast<const uint32_t*>(
            sm_dyn + (c % NSTAGE) * STF);
        const uint32_t* Bsu = Asu + AFL;
#pragma unroll
        for (int kk = 0; kk < KC; kk += 8) {
            uint32_t a[4][4], bfr[4][2];
#pragma unroll
            for (int ma = 0; ma < 4; ma++) {
                const int r = wm * 64 + ma * 16 + gid;
                a[ma][0] = Asu[r * APADW + kk + tig];
                a[ma][1] = Asu[(r + 8) * APADW + kk + tig];
                a[ma][2] = Asu[r * APADW + kk + 4 + tig];
                a[ma][3] = Asu[(r + 8) * APADW + kk + 4 + tig];
            }
#pragma unroll
            for (int na = 0; na < 4; na++) {
                const int n = wn * 32 + na * 8 + gid;
                bfr[na][0] = Bsu[(kk + tig) * BPADW + n];
                bfr[na][1] = Bsu[(kk + tig + 4) * BPADW + n];
            }
#pragma unroll
            for (int ma = 0; ma < 4; ma++)
#pragma unroll
                for (int na = 0; na < 4; na++)
                    mma_tf32(acc[ma][na], a[ma][0], a[ma][1], a[ma][2], a[ma][3],
                             bfr[na][0], bfr[na][1]);
        }
    }

    // ---- epilogue: sigmoid + store ----
#pragma unroll
    for (int ma = 0; ma < 4; ma++) {
#pragma unroll
        for (int na = 0; na < 4; na++) {
            const int row = bm + wm * 64 + ma * 16 + gid;
            const int col = bn + wn * 32 + na * 8 + 2 * tig;
            float2 v0, v1;
            v0.x = 1.f / (1.f + __expf(-acc[ma][na][0]));
            v0.y = 1.f / (1.f + __expf(-acc[ma][na][1]));
            v1.x = 1.f / (1.f + __expf(-acc[ma][na][2]));
            v1.y = 1.f / (1.f + __expf(-acc[ma][na][3]));
            *reinterpret_cast<float2*>(out + (size_t)row * DIM + col) = v0;
            *reinterpret_cast<float2*>(out + (size_t)(row + 8) * DIM + col) = v1;
        }
    }
}

extern "C" void kernel_launch(void* const* d_in, const int* in_sizes, int n_in,
                              void* d_out, int out_size) {
    const float* x  = (const float*)d_in[0];   // (4, 2048, 512) fp32
    const float* Wc = (const float*)d_in[1];   // (1024, 512) fp32
    float* out = (float*)d_out;                // (4, 2048, 512) fp32

    const size_t attn_smem = (size_t)(SROWS * TP2 + QT * SP) * sizeof(float); // 112,640 B
    cudaFuncSetAttribute(attn_kernel, cudaFuncAttributeMaxDynamicSharedMemorySize,
                         (int)attn_smem);
    attn_kernel<<<BATCH * (SEQ / QT), 256, attn_smem>>>(x);

    const size_t gemm_smem = (size_t)(NSTAGE * STF) * sizeof(float);  // 107,520 B
    cudaFuncSetAttribute(gemm_mma, cudaFuncAttributeMaxDynamicSharedMemorySize,
                         (int)gemm_smem);
    dim3 grid(DIM / GN, (BATCH * SEQ) / GM);   // (4, 64)
    gemm_mma<<<grid, 256, gemm_smem>>>(x, Wc, out);
}

// round 9
// speedup vs baseline: 1.2161x; 1.0345x over previous
#include <cuda_runtime.h>
#include <cstdint>
#include <math.h>

// ---------------- problem constants ----------------
#define BATCH 4
#define SEQ   2048
#define DIM   512
#define WIN   64
#define QT    32

// attention smem layout (D processed in 2 chunks of 256)
#define DC    256              // d-chunk width
#define TP2   260              // tile row pitch (floats); 260%32=4 -> conflict-free LDS.128
#define SROWS 96
#define SP    100              // score row pitch

// gemm tiling (mma.sync tf32 m16n8k8), fused K=1024
#define GM 128
#define GN 128
#define KC 32
#define NCHUNK (1024 / KC)     // 32
#define APADW 36
#define BPADW 136              // b-frag banks 8*tig+gid all distinct
#define AFL (GM * APADW)       // 4608
#define BFL (KC * BPADW)       // 4352
#define STF (AFL + BFL)        // 8960 floats per stage
#define NSTAGE 3

// context scratch [B*S, D] fp32 (no cudaMalloc allowed)
__device__ float g_c[BATCH * SEQ * DIM];

__device__ __forceinline__ uint32_t smem_u32(const void* p) {
    uint32_t a;
    asm("{ .reg .u64 t; cvta.to.shared.u64 t, %1; cvt.u32.u64 %0, t; }"
        : "=r"(a) : "l"(p));
    return a;
}
__device__ __forceinline__ void cpa16(uint32_t d, const float* s) {
    asm volatile("cp.async.cg.shared.global [%0], [%1], 16;" :: "r"(d), "l"(s));
}
__device__ __forceinline__ void ldsm_x4(uint32_t& r0, uint32_t& r1,
                                        uint32_t& r2, uint32_t& r3, uint32_t addr) {
    asm volatile("ldmatrix.sync.aligned.m8n8.x4.shared.b16 {%0,%1,%2,%3}, [%4];"
                 : "=r"(r0), "=r"(r1), "=r"(r2), "=r"(r3) : "r"(addr));
}

extern __shared__ float sm_dyn[];

// ---------------------------------------------------------------------------
// Attention: 256 CTAs, 256 threads, QT=32 queries each, 2 CTAs/SM.
// Band-only phase 1: per warp, 64 aligned band columns in the main loop +
// 4-column tail via lane-pair dot products. Phase 2's dense zero-fill covers
// everything outside the band, so phases 2/3 are unchanged.
// ---------------------------------------------------------------------------
__global__ __launch_bounds__(256, 2) void attn_kernel(const float* __restrict__ x) {
    float* tile = sm_dyn;                 // [96][TP2]
    float* S    = sm_dyn + SROWS * TP2;   // [32][SP]

    const int tid = threadIdx.x;
    const int b   = blockIdx.x >> 6;
    const int qs  = (blockIdx.x & 63) * QT;
    const float* xb = x + (size_t)b * SEQ * DIM;

    const int ty = tid >> 5;     // warp id (queries 4ty..4ty+3)
    const int tx = tid & 31;     // lane

    // tail work assignment: lane = ii*8 + c*2 + h
    const int t_ii = tx >> 3;            // query sub-index 0..3
    const int t_c  = (tx >> 1) & 3;      // tail column 0..3
    const int t_h  = tx & 1;             // which 256-dim half

    auto load_tile = [&](int d0) {
#pragma unroll 8
        for (int p = 0; p < 24; p++) {
            const int idx = tid + 256 * p;
            const int r   = idx >> 6;
            const int c4  = (idx & 63) << 2;
            const int gr  = qs - WIN + r;
            float4 v = make_float4(0.f, 0.f, 0.f, 0.f);
            if (gr >= 0)
                v = *reinterpret_cast<const float4*>(xb + (size_t)gr * DIM + d0 + c4);
            *reinterpret_cast<float4*>(tile + r * TP2 + c4) = v;
        }
    };

    // ---- phase 1: band scores ----
    float sa[4][2];
#pragma unroll
    for (int i = 0; i < 4; i++) { sa[i][0] = 0.f; sa[i][1] = 0.f; }
    float st = 0.f;   // tail accumulator

#pragma unroll
    for (int ch = 0; ch < 2; ch++) {
        if (ch) __syncthreads();
        load_tile(ch * DC);
        __syncthreads();

        const float* q0 = tile + (WIN + 4 * ty) * TP2;
        const float* k0 = tile + (4 * ty + tx) * TP2;      // band cols j = 4ty+tx+32g
#pragma unroll 2
        for (int d = 0; d < DC; d += 4) {
            float4 q[4], k[2];
#pragma unroll
            for (int ii = 0; ii < 4; ii++)
                q[ii] = *reinterpret_cast<const float4*>(q0 + ii * TP2 + d);
#pragma unroll
            for (int g = 0; g < 2; g++)
                k[g] = *reinterpret_cast<const float4*>(k0 + g * 32 * TP2 + d);
#pragma unroll
            for (int ii = 0; ii < 4; ii++)
#pragma unroll
                for (int g = 0; g < 2; g++) {
                    sa[ii][g] = fmaf(q[ii].x, k[g].x, sa[ii][g]);
                    sa[ii][g] = fmaf(q[ii].y, k[g].y, sa[ii][g]);
                    sa[ii][g] = fmaf(q[ii].z, k[g].z, sa[ii][g]);
                    sa[ii][g] = fmaf(q[ii].w, k[g].w, sa[ii][g]);
                }
        }
        // tail: cols 4ty+64+c for queries 4ty+ii; lane covers half h == ch
        if (t_h == ch) {
            const float* qr = tile + (WIN + 4 * ty + t_ii) * TP2;
            const float* kr = tile + (WIN + 4 * ty + t_c) * TP2;
#pragma unroll 4
            for (int d = 0; d < DC; d += 4) {
                float4 qa = *reinterpret_cast<const float4*>(qr + d);
                float4 ka = *reinterpret_cast<const float4*>(kr + d);
                st = fmaf(qa.x, ka.x, st);
                st = fmaf(qa.y, ka.y, st);
                st = fmaf(qa.z, ka.z, st);
                st = fmaf(qa.w, ka.w, st);
            }
        }
    }
    st += __shfl_xor_sync(0xffffffffu, st, 1);
#pragma unroll
    for (int ii = 0; ii < 4; ii++)
#pragma unroll
        for (int g = 0; g < 2; g++)
            S[(4 * ty + ii) * SP + 4 * ty + tx + 32 * g] = sa[ii][g];
    if (t_h == 0)
        S[(4 * ty + t_ii) * SP + 4 * ty + 64 + t_c] = st;
    __syncthreads();

    // ---- phase 2: band softmax in-place -> dense alpha (zeros outside band) ----
    {
        const int i = tid >> 3;
        const int g = tid & 7;
        float* srow = S + i * SP;
        float m = -1e30f;
        float vals[8];
#pragma unroll
        for (int w8 = 0; w8 < 8; w8++) {
            vals[w8] = srow[i + g + 8 * w8];   // j = i + w, w in [0,64)
            m = fmaxf(m, vals[w8]);
        }
        m = fmaxf(m, __shfl_xor_sync(0xffffffffu, m, 1));
        m = fmaxf(m, __shfl_xor_sync(0xffffffffu, m, 2));
        m = fmaxf(m, __shfl_xor_sync(0xffffffffu, m, 4));
        float s = 0.f;
#pragma unroll
        for (int w8 = 0; w8 < 8; w8++) s += __expf(vals[w8] - m);
        s += __shfl_xor_sync(0xffffffffu, s, 1);
        s += __shfl_xor_sync(0xffffffffu, s, 2);
        s += __shfl_xor_sync(0xffffffffu, s, 4);
        const float inv = 1.f / s;
        __syncwarp();
#pragma unroll
        for (int jj = 0; jj < 12; jj++) {
            const int j = g * 12 + jj;
            float v = 0.f;
            if (j >= i && j < i + WIN) v = __expf(srow[j] - m) * inv;
            srow[j] = v;
        }
    }

    // ---- phase 3: context per d-chunk ----
#pragma unroll
    for (int ch = 0; ch < 2; ch++) {
        __syncthreads();
        load_tile(ch * DC);
        __syncthreads();

        float cacc[4][8];
#pragma unroll
        for (int i = 0; i < 4; i++)
#pragma unroll
            for (int d = 0; d < 8; d++) cacc[i][d] = 0.f;

        const float* arow = S + 4 * ty * SP;
        for (int j = 0; j < 68; j++) {
            const int jj = 4 * ty + j;
            float a[4];
#pragma unroll
            for (int ii = 0; ii < 4; ii++) a[ii] = arow[ii * SP + jj];
            const float* kr = tile + jj * TP2 + 4 * tx;
#pragma unroll
            for (int q = 0; q < 2; q++) {
                float4 kv = *reinterpret_cast<const float4*>(kr + 128 * q);
#pragma unroll
                for (int ii = 0; ii < 4; ii++) {
                    cacc[ii][4 * q + 0] = fmaf(a[ii], kv.x, cacc[ii][4 * q + 0]);
                    cacc[ii][4 * q + 1] = fmaf(a[ii], kv.y, cacc[ii][4 * q + 1]);
                    cacc[ii][4 * q + 2] = fmaf(a[ii], kv.z, cacc[ii][4 * q + 2]);
                    cacc[ii][4 * q + 3] = fmaf(a[ii], kv.w, cacc[ii][4 * q + 3]);
                }
            }
        }
#pragma unroll
        for (int ii = 0; ii < 4; ii++) {
            float* crow = g_c + ((size_t)b * SEQ + qs + 4 * ty + ii) * DIM
                        + ch * DC + 4 * tx;
#pragma unroll
            for (int q = 0; q < 2; q++) {
                float4 v = make_float4(cacc[ii][4 * q], cacc[ii][4 * q + 1],
                                       cacc[ii][4 * q + 2], cacc[ii][4 * q + 3]);
                *reinterpret_cast<float4*>(crow + 128 * q) = v;
            }
        }
    }
}

// ---------------------------------------------------------------------------
// Output head: out = sigmoid([c | x] @ Wc) via mma.sync tf32 m16n8k8.
// CTA 128x128, 256 threads, warp tile 64x32, 3-stage cp.async.
// A-fragments via ldmatrix.x4 (4 LDSM replace 16 LDS.32 per kk-step).
// ---------------------------------------------------------------------------
__device__ __forceinline__ void mma_tf32(float* c, uint32_t a0, uint32_t a1,
                                         uint32_t a2, uint32_t a3,
                                         uint32_t b0, uint32_t b1) {
    asm volatile(
        "mma.sync.aligned.m16n8k8.row.col.f32.tf32.tf32.f32 "
        "{%0,%1,%2,%3}, {%4,%5,%6,%7}, {%8,%9}, {%0,%1,%2,%3};"
        : "+f"(c[0]), "+f"(c[1]), "+f"(c[2]), "+f"(c[3])
        : "r"(a0), "r"(a1), "r"(a2), "r"(a3), "r"(b0), "r"(b1));
}

__device__ __forceinline__ void issue_chunk(int c, int bm, int bn, int tid,
                                            const float* __restrict__ x,
                                            const float* __restrict__ Wc) {
    float* Ad = sm_dyn + (c % NSTAGE) * STF;
    float* Bd = Ad + AFL;
    const float* Asrc = (c < 16) ? g_c : x;
    const int koff = (c < 16) ? c * KC : c * KC - 512;
#pragma unroll
    for (int p = 0; p < 4; p++) {
        const int idx = tid + 256 * p;
        const int r   = idx >> 3;
        const int seg = (idx & 7) * 4;
        cpa16(smem_u32(Ad + r * APADW + seg),
              Asrc + (size_t)(bm + r) * DIM + koff + seg);
    }
#pragma unroll
    for (int p = 0; p < 4; p++) {
        const int idx = tid + 256 * p;
        const int k   = idx >> 5;
        const int n4  = (idx & 31) * 4;
        cpa16(smem_u32(Bd + k * BPADW + n4),
              Wc + (size_t)(c * KC + k) * DIM + bn + n4);
    }
    asm volatile("cp.async.commit_group;" ::: "memory");
}

__global__ __launch_bounds__(256, 2) void gemm_mma(const float* __restrict__ x,
                                                   const float* __restrict__ Wc,
                                                   float* __restrict__ out) {
    const int tid  = threadIdx.x;
    const int wid  = tid >> 5;
    const int lane = tid & 31;
    const int gid  = lane >> 2;
    const int tig  = lane & 3;
    const int wm   = wid & 1;
    const int wn   = wid >> 1;
    const int bm   = blockIdx.y * GM;
    const int bn   = blockIdx.x * GN;

    float acc[4][4][4];
#pragma unroll
    for (int i = 0; i < 4; i++)
#pragma unroll
        for (int j = 0; j < 4; j++)
#pragma unroll
            for (int k = 0; k < 4; k++) acc[i][j][k] = 0.f;

    // per-lane ldmatrix address offset within the A tile:
    // row = wm*64 + ma*16 + (lane&15), col = kk + ((lane>=16) ? 4 : 0)
    const uint32_t sm_base = smem_u32(sm_dyn);
    const uint32_t a_lm_off =
        (uint32_t)(((wm * 64 + (lane & 15)) * APADW + ((lane >> 4) << 2)) * 4);

    issue_chunk(0, bm, bn, tid, x, Wc);
    issue_chunk(1, bm, bn, tid, x, Wc);

    for (int c = 0; c < NCHUNK; c++) {
        if (c == NCHUNK - 1)
            asm volatile("cp.async.wait_group 0;" ::: "memory");
        else
            asm volatile("cp.async.wait_group 1;" ::: "memory");
        __syncthreads();
        if (c + 2 < NCHUNK) issue_chunk(c + 2, bm, bn, tid, x, Wc);

        const uint32_t As_addr = sm_base + (uint32_t)((c % NSTAGE) * STF * 4);
        const uint32_t* Bsu = reinterpret_cast<const uint32_t*>(
            sm_dyn + (c % NSTAGE) * STF + AFL);
#pragma unroll
        for (int kk = 0; kk < KC; kk += 8) {
            uint32_t a[4][4], bfr[4][2];
#pragma unroll
            for (int ma = 0; ma < 4; ma++)
                ldsm_x4(a[ma][0], a[ma][1], a[ma][2], a[ma][3],
                        As_addr + a_lm_off + (uint32_t)((ma * 16 * APADW + kk) * 4));
#pragma unroll
            for (int na = 0; na < 4; na++) {
                const int n = wn * 32 + na * 8 + gid;
                bfr[na][0] = Bsu[(kk + tig) * BPADW + n];
                bfr[na][1] = Bsu[(kk + tig + 4) * BPADW + n];
            }
#pragma unroll
            for (int ma = 0; ma < 4; ma++)
#pragma unroll
                for (int na = 0; na < 4; na++)
                    mma_tf32(acc[ma][na], a[ma][0], a[ma][1], a[ma][2], a[ma][3],
                             bfr[na][0], bfr[na][1]);
        }
    }

    // ---- epilogue: sigmoid + store ----
#pragma unroll
    for (int ma = 0; ma < 4; ma++) {
#pragma unroll
        for (int na = 0; na < 4; na++) {
            const int row = bm + wm * 64 + ma * 16 + gid;
            const int col = bn + wn * 32 + na * 8 + 2 * tig;
            float2 v0, v1;
            v0.x = 1.f / (1.f + __expf(-acc[ma][na][0]));
            v0.y = 1.f / (1.f + __expf(-acc[ma][na][1]));
            v1.x = 1.f / (1.f + __expf(-acc[ma][na][2]));
            v1.y = 1.f / (1.f + __expf(-acc[ma][na][3]));
            *reinterpret_cast<float2*>(out + (size_t)row * DIM + col) = v0;
            *reinterpret_cast<float2*>(out + (size_t)(row + 8) * DIM + col) = v1;
        }
    }
}

extern "C" void kernel_launch(void* const* d_in, const int* in_sizes, int n_in,
                              void* d_out, int out_size) {
    const float* x  = (const float*)d_in[0];   // (4, 2048, 512) fp32
    const float* Wc = (const float*)d_in[1];   // (1024, 512) fp32
    float* out = (float*)d_out;                // (4, 2048, 512) fp32

    const size_t attn_smem = (size_t)(SROWS * TP2 + QT * SP) * sizeof(float); // 112,640 B
    cudaFuncSetAttribute(attn_kernel, cudaFuncAttributeMaxDynamicSharedMemorySize,
                         (int)attn_smem);
    attn_kernel<<<BATCH * (SEQ / QT), 256, attn_smem>>>(x);

    const size_t gemm_smem = (size_t)(NSTAGE * STF) * sizeof(float);  // 107,520 B
    cudaFuncSetAttribute(gemm_mma, cudaFuncAttributeMaxDynamicSharedMemorySize,
                         (int)gemm_smem);
    dim3 grid(DIM / GN, (BATCH * SEQ) / GM);   // (4, 64)
    gemm_mma<<<grid, 256, gemm_smem>>>(x, Wc, out);
}